// round 1
// baseline (speedup 1.0000x reference)
#include <cuda_runtime.h>
#include <math.h>

#define T_TOK 2048
#define DIM   1024
#define HID   2816
#define NEXP  8
#define TOPK  2

#define BM 64
#define BN 64
#define BK 16

// ---------------- scratch (device globals; no allocations allowed) ----------------
__device__ float g_h[(size_t)NEXP * T_TOK * HID];      // expert-region h buffer
__device__ float g_ypair[(size_t)NEXP * T_TOK * DIM];  // per-pair FFN output
__device__ int   g_pair_token[NEXP * T_TOK];
__device__ int   g_token_pairs[T_TOK * TOPK];          // token -> pair slot (e*T + pos)
__device__ float g_token_gate[T_TOK * TOPK];
__device__ float g_token_p[T_TOK * NEXP];              // full softmax probs per token
__device__ float g_lse[T_TOK];                         // logsumexp per token
__device__ int   g_count[NEXP];

// ---------------- kernel 0: reset counters ----------------
__global__ void zero_counts_kernel() {
    int i = threadIdx.x;
    if (i < NEXP) g_count[i] = 0;
}

// ---------------- kernel 1: router ----------------
// 1 warp per token; router weights (8x1024 = 32KB) staged in SMEM per block.
__global__ __launch_bounds__(256) void router_kernel(
    const float* __restrict__ x, const float* __restrict__ rw)
{
    __shared__ float s_rw[NEXP * DIM];
    int tid = threadIdx.x;
    for (int i = tid; i < NEXP * DIM; i += 256) s_rw[i] = rw[i];
    __syncthreads();

    int warp = tid >> 5;
    int lane = tid & 31;
    int t = blockIdx.x * 8 + warp;
    if (t >= T_TOK) return;

    const float* xp = x + (size_t)t * DIM;
    float acc[NEXP];
#pragma unroll
    for (int e = 0; e < NEXP; e++) acc[e] = 0.f;

    for (int d = lane; d < DIM; d += 32) {
        float xv = xp[d];
#pragma unroll
        for (int e = 0; e < NEXP; e++) acc[e] += xv * s_rw[e * DIM + d];
    }
#pragma unroll
    for (int e = 0; e < NEXP; e++) {
#pragma unroll
        for (int off = 16; off > 0; off >>= 1)
            acc[e] += __shfl_xor_sync(0xFFFFFFFFu, acc[e], off);
    }

    if (lane == 0) {
        // top-2 (first-index tie-break, matching jax top_k)
        int i0 = 0; float l0 = acc[0];
#pragma unroll
        for (int e = 1; e < NEXP; e++) if (acc[e] > l0) { l0 = acc[e]; i0 = e; }
        int i1 = -1; float l1 = -1e30f;
#pragma unroll
        for (int e = 0; e < NEXP; e++) if (e != i0 && acc[e] > l1) { l1 = acc[e]; i1 = e; }

        float p0 = 1.f / (1.f + expf(l1 - l0));
        float p1 = 1.f - p0;

        // full softmax + lse (l0 is the max)
        float se = 0.f;
        float pe[NEXP];
#pragma unroll
        for (int e = 0; e < NEXP; e++) { pe[e] = expf(acc[e] - l0); se += pe[e]; }
        float inv = 1.f / se;
#pragma unroll
        for (int e = 0; e < NEXP; e++) g_token_p[t * NEXP + e] = pe[e] * inv;
        g_lse[t] = l0 + logf(se);

        int pos0 = atomicAdd(&g_count[i0], 1);
        g_pair_token[i0 * T_TOK + pos0] = t;
        g_token_pairs[t * 2 + 0] = i0 * T_TOK + pos0;
        g_token_gate[t * 2 + 0] = p0;

        int pos1 = atomicAdd(&g_count[i1], 1);
        g_pair_token[i1 * T_TOK + pos1] = t;
        g_token_pairs[t * 2 + 1] = i1 * T_TOK + pos1;
        g_token_gate[t * 2 + 1] = p1;
    }
}

// ---------------- kernel 2: aux loss (deterministic single-block reduction) --------
__global__ __launch_bounds__(256) void aux_kernel(float* __restrict__ out)
{
    int tid = threadIdx.x;
    int lane = tid & 31, warp = tid >> 5;
    float lp[NEXP];
#pragma unroll
    for (int e = 0; e < NEXP; e++) lp[e] = 0.f;
    float lz = 0.f;
    for (int t = tid; t < T_TOK; t += 256) {
#pragma unroll
        for (int e = 0; e < NEXP; e++) lp[e] += g_token_p[t * NEXP + e];
        float l = g_lse[t];
        lz += l * l;
    }
#pragma unroll
    for (int e = 0; e < NEXP; e++)
#pragma unroll
        for (int off = 16; off > 0; off >>= 1)
            lp[e] += __shfl_xor_sync(0xFFFFFFFFu, lp[e], off);
#pragma unroll
    for (int off = 16; off > 0; off >>= 1)
        lz += __shfl_xor_sync(0xFFFFFFFFu, lz, off);

    __shared__ float wp[8][NEXP];
    __shared__ float wz[8];
    if (lane == 0) {
#pragma unroll
        for (int e = 0; e < NEXP; e++) wp[warp][e] = lp[e];
        wz[warp] = lz;
    }
    __syncthreads();
    if (tid == 0) {
        float psum[NEXP]; float z = 0.f;
#pragma unroll
        for (int e = 0; e < NEXP; e++) psum[e] = 0.f;
        for (int w = 0; w < 8; w++) {
#pragma unroll
            for (int e = 0; e < NEXP; e++) psum[e] += wp[w][e];
            z += wz[w];
        }
        float lb = 0.f;
#pragma unroll
        for (int e = 0; e < NEXP; e++)
            lb += ((float)g_count[e] / (float)(T_TOK * TOPK)) * (psum[e] / (float)T_TOK);
        out[(size_t)T_TOK * DIM] = 0.01f * (float)NEXP * lb + 0.001f * (z / (float)T_TOK);
    }
}

// ---------------- kernel 3: grouped GEMM stage A: h = silu(x w1^T) * (x w3^T) -----
__global__ __launch_bounds__(256) void ffn_h_kernel(
    const float* __restrict__ x,
    const float* __restrict__ w1,
    const float* __restrict__ w3)
{
    int e = blockIdx.z;
    int cnt = g_count[e];
    int m0 = blockIdx.y * BM;
    if (m0 >= cnt) return;
    int n0 = blockIdx.x * BN;

    __shared__ float As [BK][BM];
    __shared__ float B1s[BK][BN];
    __shared__ float B3s[BK][BN];

    int tid = threadIdx.x;
    int lr = tid >> 2;              // load row 0..63
    int kc = (tid & 3) * 4;         // k-chunk within BK
    int ty = tid >> 4;              // compute row group 0..15
    int tx = tid & 15;              // compute col group 0..15

    int mrow = m0 + lr;
    int tok = 0;
    bool mvalid = (mrow < cnt);
    if (mvalid) tok = g_pair_token[e * T_TOK + mrow];
    const float* aptr  = x + (size_t)tok * DIM;
    const float* b1ptr = w1 + ((size_t)e * HID + (n0 + lr)) * DIM;
    const float* b3ptr = w3 + ((size_t)e * HID + (n0 + lr)) * DIM;

    float acc1[4][4], acc3[4][4];
#pragma unroll
    for (int i = 0; i < 4; i++)
#pragma unroll
        for (int j = 0; j < 4; j++) { acc1[i][j] = 0.f; acc3[i][j] = 0.f; }

    for (int k0 = 0; k0 < DIM; k0 += BK) {
        float4 av = make_float4(0.f, 0.f, 0.f, 0.f);
        if (mvalid) av = *reinterpret_cast<const float4*>(aptr + k0 + kc);
        float4 b1v = *reinterpret_cast<const float4*>(b1ptr + k0 + kc);
        float4 b3v = *reinterpret_cast<const float4*>(b3ptr + k0 + kc);
        __syncthreads();
        As [kc+0][lr] = av.x;  As [kc+1][lr] = av.y;  As [kc+2][lr] = av.z;  As [kc+3][lr] = av.w;
        B1s[kc+0][lr] = b1v.x; B1s[kc+1][lr] = b1v.y; B1s[kc+2][lr] = b1v.z; B1s[kc+3][lr] = b1v.w;
        B3s[kc+0][lr] = b3v.x; B3s[kc+1][lr] = b3v.y; B3s[kc+2][lr] = b3v.z; B3s[kc+3][lr] = b3v.w;
        __syncthreads();
#pragma unroll
        for (int kk = 0; kk < BK; kk++) {
            float4 a  = *reinterpret_cast<const float4*>(&As [kk][ty * 4]);
            float4 b1 = *reinterpret_cast<const float4*>(&B1s[kk][tx * 4]);
            float4 b3 = *reinterpret_cast<const float4*>(&B3s[kk][tx * 4]);
            float avr[4] = {a.x, a.y, a.z, a.w};
            float b1r[4] = {b1.x, b1.y, b1.z, b1.w};
            float b3r[4] = {b3.x, b3.y, b3.z, b3.w};
#pragma unroll
            for (int i = 0; i < 4; i++)
#pragma unroll
                for (int j = 0; j < 4; j++) {
                    acc1[i][j] += avr[i] * b1r[j];
                    acc3[i][j] += avr[i] * b3r[j];
                }
        }
    }

#pragma unroll
    for (int i = 0; i < 4; i++) {
        int m = m0 + ty * 4 + i;
        if (m >= cnt) continue;
        float* hrow = g_h + ((size_t)(e * T_TOK) + m) * HID;
#pragma unroll
        for (int j = 0; j < 4; j++) {
            int n = n0 + tx * 4 + j;
            float h1 = acc1[i][j];
            float hv = h1 / (1.f + expf(-h1)) * acc3[i][j];
            hrow[n] = hv;
        }
    }
}

// ---------------- kernel 4: grouped GEMM stage B: y_pair = h w2^T ------------------
__global__ __launch_bounds__(256) void ffn_y_kernel(const float* __restrict__ w2)
{
    int e = blockIdx.z;
    int cnt = g_count[e];
    int m0 = blockIdx.y * BM;
    if (m0 >= cnt) return;
    int n0 = blockIdx.x * BN;

    __shared__ float As[BK][BM];
    __shared__ float Bs[BK][BN];

    int tid = threadIdx.x;
    int lr = tid >> 2;
    int kc = (tid & 3) * 4;
    int ty = tid >> 4;
    int tx = tid & 15;

    // rows beyond cnt read stale-but-finite scratch; their accumulators are discarded
    const float* aptr = g_h + ((size_t)(e * T_TOK) + (m0 + lr)) * HID;
    const float* bptr = w2 + ((size_t)e * DIM + (n0 + lr)) * HID;

    float acc[4][4];
#pragma unroll
    for (int i = 0; i < 4; i++)
#pragma unroll
        for (int j = 0; j < 4; j++) acc[i][j] = 0.f;

    for (int k0 = 0; k0 < HID; k0 += BK) {
        float4 av = *reinterpret_cast<const float4*>(aptr + k0 + kc);
        float4 bv = *reinterpret_cast<const float4*>(bptr + k0 + kc);
        __syncthreads();
        As[kc+0][lr] = av.x; As[kc+1][lr] = av.y; As[kc+2][lr] = av.z; As[kc+3][lr] = av.w;
        Bs[kc+0][lr] = bv.x; Bs[kc+1][lr] = bv.y; Bs[kc+2][lr] = bv.z; Bs[kc+3][lr] = bv.w;
        __syncthreads();
#pragma unroll
        for (int kk = 0; kk < BK; kk++) {
            float4 a = *reinterpret_cast<const float4*>(&As[kk][ty * 4]);
            float4 b = *reinterpret_cast<const float4*>(&Bs[kk][tx * 4]);
            float avr[4] = {a.x, a.y, a.z, a.w};
            float bvr[4] = {b.x, b.y, b.z, b.w};
#pragma unroll
            for (int i = 0; i < 4; i++)
#pragma unroll
                for (int j = 0; j < 4; j++) acc[i][j] += avr[i] * bvr[j];
        }
    }

#pragma unroll
    for (int i = 0; i < 4; i++) {
        int m = m0 + ty * 4 + i;
        if (m >= cnt) continue;
        float* yrow = g_ypair + ((size_t)(e * T_TOK) + m) * DIM;
#pragma unroll
        for (int j = 0; j < 4; j++) {
            int n = n0 + tx * 4 + j;
            yrow[n] = acc[i][j];
        }
    }
}

// ---------------- kernel 5: combine y = g0*ypair[s0] + g1*ypair[s1] ----------------
__global__ __launch_bounds__(256) void combine_kernel(float* __restrict__ out)
{
    const int D4 = DIM / 4;
    int i = blockIdx.x * blockDim.x + threadIdx.x;
    if (i >= T_TOK * D4) return;
    int t = i / D4;
    int r = i - t * D4;
    int s0 = g_token_pairs[t * 2 + 0];
    int s1 = g_token_pairs[t * 2 + 1];
    float g0 = g_token_gate[t * 2 + 0];
    float g1 = g_token_gate[t * 2 + 1];
    const float4* y0 = reinterpret_cast<const float4*>(g_ypair) + (size_t)s0 * D4 + r;
    const float4* y1 = reinterpret_cast<const float4*>(g_ypair) + (size_t)s1 * D4 + r;
    float4 a = *y0, b = *y1, o;
    o.x = g0 * a.x + g1 * b.x;
    o.y = g0 * a.y + g1 * b.y;
    o.z = g0 * a.z + g1 * b.z;
    o.w = g0 * a.w + g1 * b.w;
    reinterpret_cast<float4*>(out)[i] = o;
}

// ---------------- launch ----------------
extern "C" void kernel_launch(void* const* d_in, const int* in_sizes, int n_in,
                              void* d_out, int out_size) {
    (void)in_sizes; (void)n_in; (void)out_size;
    const float* x  = (const float*)d_in[0];
    const float* rw = (const float*)d_in[1];
    const float* w1 = (const float*)d_in[2];
    const float* w3 = (const float*)d_in[3];
    const float* w2 = (const float*)d_in[4];
    float* out = (float*)d_out;

    zero_counts_kernel<<<1, 32>>>();
    router_kernel<<<T_TOK / 8, 256>>>(x, rw);
    aux_kernel<<<1, 256>>>(out);
    ffn_h_kernel<<<dim3(HID / BN, T_TOK / BM, NEXP), 256>>>(x, w1, w3);
    ffn_y_kernel<<<dim3(DIM / BN, T_TOK / BM, NEXP), 256>>>(w2);
    combine_kernel<<<(T_TOK * (DIM / 4) + 255) / 256, 256>>>(out);
}

// round 5
// speedup vs baseline: 2.4160x; 2.4160x over previous
#include <cuda_runtime.h>
#include <cuda_bf16.h>
#include <stdint.h>
#include <math.h>

#define T_TOK 2048
#define DIM   1024
#define HID   2816
#define NEXP  8
#define TOPK  2
#define SP    40      // padded SMEM row stride in bf16 elems (80 bytes)

// ---------------- scratch (device globals; no allocations allowed) ----------------
__device__ __nv_bfloat16 g_h_hi[(size_t)NEXP * T_TOK * HID];   // SwiGLU h, bf16 hi
__device__ __nv_bfloat16 g_h_lo[(size_t)NEXP * T_TOK * HID];   // SwiGLU h, bf16 lo
__device__ float g_ypair[(size_t)NEXP * T_TOK * DIM];          // per-pair FFN output
__device__ int   g_pair_token[NEXP * T_TOK];
__device__ int   g_token_pairs[T_TOK * TOPK];
__device__ float g_token_gate[T_TOK * TOPK];
__device__ float g_token_p[T_TOK * NEXP];
__device__ float g_lse[T_TOK];
__device__ int   g_count[NEXP];

// ============================ helpers ============================
__device__ __forceinline__ uint32_t smem_u32(const void* p) {
    uint32_t a;
    asm("{ .reg .u64 t; cvta.to.shared.u64 t, %1; cvt.u32.u64 %0, t; }" : "=r"(a) : "l"(p));
    return a;
}
__device__ __forceinline__ void ldsm4(uint32_t& r0, uint32_t& r1, uint32_t& r2, uint32_t& r3,
                                      uint32_t addr) {
    asm volatile("ldmatrix.sync.aligned.m8n8.x4.shared.b16 {%0,%1,%2,%3}, [%4];"
        : "=r"(r0), "=r"(r1), "=r"(r2), "=r"(r3) : "r"(addr));
}
__device__ __forceinline__ void mma_bf16(float* d, const uint32_t* a, uint32_t b0, uint32_t b1) {
    asm volatile("mma.sync.aligned.m16n8k16.row.col.f32.bf16.bf16.f32 "
        "{%0,%1,%2,%3}, {%4,%5,%6,%7}, {%8,%9}, {%0,%1,%2,%3};"
        : "+f"(d[0]), "+f"(d[1]), "+f"(d[2]), "+f"(d[3])
        : "r"(a[0]), "r"(a[1]), "r"(a[2]), "r"(a[3]), "r"(b0), "r"(b1));
}
__device__ __forceinline__ unsigned short bf_hi_us(float f) {
    return __bfloat16_as_ushort(__float2bfloat16_rn(f));
}
__device__ __forceinline__ float bf_us_f(unsigned short u) {
    return __bfloat162float(__ushort_as_bfloat16(u));
}
__device__ __forceinline__ void split4(float4 v, uint2& hi, uint2& lo) {
    unsigned short h0 = bf_hi_us(v.x), h1 = bf_hi_us(v.y), h2 = bf_hi_us(v.z), h3 = bf_hi_us(v.w);
    unsigned short l0 = bf_hi_us(v.x - bf_us_f(h0));
    unsigned short l1 = bf_hi_us(v.y - bf_us_f(h1));
    unsigned short l2 = bf_hi_us(v.z - bf_us_f(h2));
    unsigned short l3 = bf_hi_us(v.w - bf_us_f(h3));
    hi.x = (uint32_t)h0 | ((uint32_t)h1 << 16);
    hi.y = (uint32_t)h2 | ((uint32_t)h3 << 16);
    lo.x = (uint32_t)l0 | ((uint32_t)l1 << 16);
    lo.y = (uint32_t)l2 | ((uint32_t)l3 << 16);
}

// ============================ router & aux ============================
__global__ void zero_counts_kernel() {
    int i = threadIdx.x;
    if (i < NEXP) g_count[i] = 0;
}

__global__ __launch_bounds__(256) void router_kernel(
    const float* __restrict__ x, const float* __restrict__ rw)
{
    __shared__ float s_rw[NEXP * DIM];
    int tid = threadIdx.x;
    for (int i = tid; i < NEXP * DIM; i += 256) s_rw[i] = rw[i];
    __syncthreads();

    int warp = tid >> 5, lane = tid & 31;
    int t = blockIdx.x * 8 + warp;
    if (t >= T_TOK) return;

    const float* xp = x + (size_t)t * DIM;
    float acc[NEXP];
#pragma unroll
    for (int e = 0; e < NEXP; e++) acc[e] = 0.f;
    for (int d = lane; d < DIM; d += 32) {
        float xv = xp[d];
#pragma unroll
        for (int e = 0; e < NEXP; e++) acc[e] += xv * s_rw[e * DIM + d];
    }
#pragma unroll
    for (int e = 0; e < NEXP; e++)
#pragma unroll
        for (int off = 16; off > 0; off >>= 1)
            acc[e] += __shfl_xor_sync(0xFFFFFFFFu, acc[e], off);

    if (lane == 0) {
        int i0 = 0; float l0 = acc[0];
#pragma unroll
        for (int e = 1; e < NEXP; e++) if (acc[e] > l0) { l0 = acc[e]; i0 = e; }
        int i1 = -1; float l1 = -1e30f;
#pragma unroll
        for (int e = 0; e < NEXP; e++) if (e != i0 && acc[e] > l1) { l1 = acc[e]; i1 = e; }

        float p0 = 1.f / (1.f + expf(l1 - l0));
        float p1 = 1.f - p0;

        float se = 0.f, pe[NEXP];
#pragma unroll
        for (int e = 0; e < NEXP; e++) { pe[e] = expf(acc[e] - l0); se += pe[e]; }
        float inv = 1.f / se;
#pragma unroll
        for (int e = 0; e < NEXP; e++) g_token_p[t * NEXP + e] = pe[e] * inv;
        g_lse[t] = l0 + logf(se);

        int pos0 = atomicAdd(&g_count[i0], 1);
        g_pair_token[i0 * T_TOK + pos0] = t;
        g_token_pairs[t * 2 + 0] = i0 * T_TOK + pos0;
        g_token_gate[t * 2 + 0] = p0;

        int pos1 = atomicAdd(&g_count[i1], 1);
        g_pair_token[i1 * T_TOK + pos1] = t;
        g_token_pairs[t * 2 + 1] = i1 * T_TOK + pos1;
        g_token_gate[t * 2 + 1] = p1;
    }
}

__global__ __launch_bounds__(256) void aux_kernel(float* __restrict__ out)
{
    int tid = threadIdx.x, lane = tid & 31, warp = tid >> 5;
    float lp[NEXP];
#pragma unroll
    for (int e = 0; e < NEXP; e++) lp[e] = 0.f;
    float lz = 0.f;
    for (int t = tid; t < T_TOK; t += 256) {
#pragma unroll
        for (int e = 0; e < NEXP; e++) lp[e] += g_token_p[t * NEXP + e];
        float l = g_lse[t];
        lz += l * l;
    }
#pragma unroll
    for (int e = 0; e < NEXP; e++)
#pragma unroll
        for (int off = 16; off > 0; off >>= 1)
            lp[e] += __shfl_xor_sync(0xFFFFFFFFu, lp[e], off);
#pragma unroll
    for (int off = 16; off > 0; off >>= 1)
        lz += __shfl_xor_sync(0xFFFFFFFFu, lz, off);

    __shared__ float wp[8][NEXP];
    __shared__ float wz[8];
    if (lane == 0) {
#pragma unroll
        for (int e = 0; e < NEXP; e++) wp[warp][e] = lp[e];
        wz[warp] = lz;
    }
    __syncthreads();
    if (tid == 0) {
        float psum[NEXP]; float z = 0.f;
#pragma unroll
        for (int e = 0; e < NEXP; e++) psum[e] = 0.f;
        for (int w = 0; w < 8; w++) {
#pragma unroll
            for (int e = 0; e < NEXP; e++) psum[e] += wp[w][e];
            z += wz[w];
        }
        float lb = 0.f;
#pragma unroll
        for (int e = 0; e < NEXP; e++)
            lb += ((float)g_count[e] / (float)(T_TOK * TOPK)) * (psum[e] / (float)T_TOK);
        out[(size_t)T_TOK * DIM] = 0.01f * (float)NEXP * lb + 0.001f * (z / (float)T_TOK);
    }
}

// ============================ stage A: h = silu(x w1^T) * (x w3^T) ============================
// CTA tile 128m x 64n, BK=32, 8 warps (4m x 2n), 3-pass bf16-split HMMA.
__global__ __launch_bounds__(256) void ffn_h_mma(
    const float* __restrict__ x,
    const float* __restrict__ w1,
    const float* __restrict__ w3)
{
    __shared__ __align__(16) unsigned short sAh[128 * SP], sAl[128 * SP];
    __shared__ __align__(16) unsigned short sB1h[64 * SP], sB1l[64 * SP];
    __shared__ __align__(16) unsigned short sB3h[64 * SP], sB3l[64 * SP];
    __shared__ int s_tok[128];

    const int e = blockIdx.z;
    const int cnt = g_count[e];
    const int m0 = blockIdx.y * 128;
    if (m0 >= cnt) return;
    const int n0 = blockIdx.x * 64;
    const int tid = threadIdx.x;
    const int rem = cnt - m0;

    if (tid < 128) {
        int m = m0 + tid;
        s_tok[tid] = (m < cnt) ? g_pair_token[e * T_TOK + m] : 0;
    }
    __syncthreads();

    const int lr = tid >> 3;          // 0..31 (+32*i)
    const int lc = (tid & 7) * 4;     // element col within BK

    int tokr[4];
#pragma unroll
    for (int i = 0; i < 4; i++) tokr[i] = s_tok[lr + 32 * i];

    const float* b1base = w1 + ((size_t)e * HID + n0) * DIM;
    const float* b3base = w3 + ((size_t)e * HID + n0) * DIM;

    const int warp = tid >> 5, lane = tid & 31;
    const int wm = warp >> 1, wn = warp & 1;
    const int mb = wm * 32, nb = wn * 32;
    const int mat = lane >> 3, lrow = lane & 7;
    const int m_half = (mat & 1) * 8, k_half_a = (mat >> 1) * 8;
    const int n_half = (mat >> 1) * 8, k_half_b = (mat & 1) * 8;

    const uint32_t uAh = smem_u32(sAh), uAl = smem_u32(sAl);
    const uint32_t uB1h = smem_u32(sB1h), uB1l = smem_u32(sB1l);
    const uint32_t uB3h = smem_u32(sB3h), uB3l = smem_u32(sB3l);

    // ldmatrix per-lane base offsets (bytes), k part added per kstep
    const uint32_t aoff0 = (uint32_t)(((mb + m_half + lrow) * SP + k_half_a) * 2);
    const uint32_t boff0 = (uint32_t)(((nb + n_half + lrow) * SP + k_half_b) * 2);

    float acc1[2][4][4], acc3[2][4][4];
#pragma unroll
    for (int a = 0; a < 2; a++)
#pragma unroll
        for (int b = 0; b < 4; b++)
#pragma unroll
            for (int c = 0; c < 4; c++) { acc1[a][b][c] = 0.f; acc3[a][b][c] = 0.f; }

    float4 aR[4], b1R[2], b3R[2];
    // prologue loads (kc = 0)
#pragma unroll
    for (int i = 0; i < 4; i++) {
        int r = lr + 32 * i;
        float4 v = make_float4(0.f, 0.f, 0.f, 0.f);
        if (r < rem) v = *reinterpret_cast<const float4*>(x + (size_t)tokr[i] * DIM + lc);
        aR[i] = v;
    }
#pragma unroll
    for (int i = 0; i < 2; i++) {
        int r = lr + 32 * i;
        b1R[i] = *reinterpret_cast<const float4*>(b1base + (size_t)r * DIM + lc);
        b3R[i] = *reinterpret_cast<const float4*>(b3base + (size_t)r * DIM + lc);
    }

    for (int kc = 0; kc < DIM / 32; kc++) {
        __syncthreads();
        // store split tiles
#pragma unroll
        for (int i = 0; i < 4; i++) {
            uint2 h, l; split4(aR[i], h, l);
            int r = lr + 32 * i;
            *reinterpret_cast<uint2*>(&sAh[r * SP + lc]) = h;
            *reinterpret_cast<uint2*>(&sAl[r * SP + lc]) = l;
        }
#pragma unroll
        for (int i = 0; i < 2; i++) {
            int r = lr + 32 * i;
            uint2 h, l;
            split4(b1R[i], h, l);
            *reinterpret_cast<uint2*>(&sB1h[r * SP + lc]) = h;
            *reinterpret_cast<uint2*>(&sB1l[r * SP + lc]) = l;
            split4(b3R[i], h, l);
            *reinterpret_cast<uint2*>(&sB3h[r * SP + lc]) = h;
            *reinterpret_cast<uint2*>(&sB3l[r * SP + lc]) = l;
        }
        __syncthreads();

        // issue next tile's loads (latency hidden under MMA below)
        if (kc + 1 < DIM / 32) {
            int k0 = (kc + 1) * 32;
#pragma unroll
            for (int i = 0; i < 4; i++) {
                int r = lr + 32 * i;
                float4 v = make_float4(0.f, 0.f, 0.f, 0.f);
                if (r < rem) v = *reinterpret_cast<const float4*>(x + (size_t)tokr[i] * DIM + k0 + lc);
                aR[i] = v;
            }
#pragma unroll
            for (int i = 0; i < 2; i++) {
                int r = lr + 32 * i;
                b1R[i] = *reinterpret_cast<const float4*>(b1base + (size_t)r * DIM + k0 + lc);
                b3R[i] = *reinterpret_cast<const float4*>(b3base + (size_t)r * DIM + k0 + lc);
            }
        }

#pragma unroll
        for (int ks = 0; ks < 2; ks++) {
            const uint32_t kb = (uint32_t)(ks * 32);   // 16 elems * 2B
            uint32_t ah[2][4], al[2][4];
#pragma unroll
            for (int mt = 0; mt < 2; mt++) {
                uint32_t off = aoff0 + (uint32_t)(mt * 16 * SP * 2) + kb;
                ldsm4(ah[mt][0], ah[mt][1], ah[mt][2], ah[mt][3], uAh + off);
                ldsm4(al[mt][0], al[mt][1], al[mt][2], al[mt][3], uAl + off);
            }
            uint32_t b1h[2][4], b1l[2][4], b3h[2][4], b3l[2][4];
#pragma unroll
            for (int np = 0; np < 2; np++) {
                uint32_t off = boff0 + (uint32_t)(np * 16 * SP * 2) + kb;
                ldsm4(b1h[np][0], b1h[np][1], b1h[np][2], b1h[np][3], uB1h + off);
                ldsm4(b1l[np][0], b1l[np][1], b1l[np][2], b1l[np][3], uB1l + off);
                ldsm4(b3h[np][0], b3h[np][1], b3h[np][2], b3h[np][3], uB3h + off);
                ldsm4(b3l[np][0], b3l[np][1], b3l[np][2], b3l[np][3], uB3l + off);
            }
#pragma unroll
            for (int mt = 0; mt < 2; mt++) {
#pragma unroll
                for (int nt = 0; nt < 4; nt++) {
                    int np = nt >> 1, s = (nt & 1) * 2;
                    mma_bf16(acc1[mt][nt], ah[mt], b1h[np][s], b1h[np][s + 1]);
                    mma_bf16(acc1[mt][nt], ah[mt], b1l[np][s], b1l[np][s + 1]);
                    mma_bf16(acc1[mt][nt], al[mt], b1h[np][s], b1h[np][s + 1]);
                    mma_bf16(acc3[mt][nt], ah[mt], b3h[np][s], b3h[np][s + 1]);
                    mma_bf16(acc3[mt][nt], ah[mt], b3l[np][s], b3l[np][s + 1]);
                    mma_bf16(acc3[mt][nt], al[mt], b3h[np][s], b3h[np][s + 1]);
                }
            }
        }
    }

    // epilogue: SwiGLU + bf16 split, write h
    const int er = lane >> 2;        // 0..7
    const int ec = (lane & 3) * 2;   // 0,2,4,6
#pragma unroll
    for (int mt = 0; mt < 2; mt++) {
#pragma unroll
        for (int half = 0; half < 2; half++) {
            int m = m0 + mb + mt * 16 + er + half * 8;
            if (m >= cnt) continue;
            size_t base = (size_t)((e * T_TOK) + m) * HID;
#pragma unroll
            for (int nt = 0; nt < 4; nt++) {
                float f1a = acc1[mt][nt][half * 2 + 0];
                float f1b = acc1[mt][nt][half * 2 + 1];
                float f3a = acc3[mt][nt][half * 2 + 0];
                float f3b = acc3[mt][nt][half * 2 + 1];
                float ha = f1a / (1.f + __expf(-f1a)) * f3a;
                float hb = f1b / (1.f + __expf(-f1b)) * f3b;
                unsigned short hha = bf_hi_us(ha), hhb = bf_hi_us(hb);
                unsigned short lla = bf_hi_us(ha - bf_us_f(hha));
                unsigned short llb = bf_hi_us(hb - bf_us_f(hhb));
                int col = n0 + nb + nt * 8 + ec;
                *reinterpret_cast<uint32_t*>(&g_h_hi[base + col]) =
                    (uint32_t)hha | ((uint32_t)hhb << 16);
                *reinterpret_cast<uint32_t*>(&g_h_lo[base + col]) =
                    (uint32_t)lla | ((uint32_t)llb << 16);
            }
        }
    }
}

// ============================ stage B: y_pair = h w2^T ============================
__global__ __launch_bounds__(256) void ffn_y_mma(const float* __restrict__ w2)
{
    __shared__ __align__(16) unsigned short sAh[128 * SP], sAl[128 * SP];
    __shared__ __align__(16) unsigned short sBh[64 * SP], sBl[64 * SP];

    const int e = blockIdx.z;
    const int cnt = g_count[e];
    const int m0 = blockIdx.y * 128;
    if (m0 >= cnt) return;
    const int n0 = blockIdx.x * 64;
    const int tid = threadIdx.x;

    const int lr = tid >> 3;
    const int lc = (tid & 7) * 4;

    const __nv_bfloat16* ahg = g_h_hi + ((size_t)(e * T_TOK + m0)) * HID;
    const __nv_bfloat16* alg = g_h_lo + ((size_t)(e * T_TOK + m0)) * HID;
    const float* bbase = w2 + ((size_t)e * DIM + n0) * HID;

    const int warp = tid >> 5, lane = tid & 31;
    const int wm = warp >> 1, wn = warp & 1;
    const int mb = wm * 32, nb = wn * 32;
    const int mat = lane >> 3, lrow = lane & 7;
    const int m_half = (mat & 1) * 8, k_half_a = (mat >> 1) * 8;
    const int n_half = (mat >> 1) * 8, k_half_b = (mat & 1) * 8;

    const uint32_t uAh = smem_u32(sAh), uAl = smem_u32(sAl);
    const uint32_t uBh = smem_u32(sBh), uBl = smem_u32(sBl);
    const uint32_t aoff0 = (uint32_t)(((mb + m_half + lrow) * SP + k_half_a) * 2);
    const uint32_t boff0 = (uint32_t)(((nb + n_half + lrow) * SP + k_half_b) * 2);

    float acc[2][4][4];
#pragma unroll
    for (int a = 0; a < 2; a++)
#pragma unroll
        for (int b = 0; b < 4; b++)
#pragma unroll
            for (int c = 0; c < 4; c++) acc[a][b][c] = 0.f;

    uint2 aHR[4], aLR[4];
    float4 bR[2];
#pragma unroll
    for (int i = 0; i < 4; i++) {
        size_t off = (size_t)(lr + 32 * i) * HID + lc;
        aHR[i] = *reinterpret_cast<const uint2*>(ahg + off);
        aLR[i] = *reinterpret_cast<const uint2*>(alg + off);
    }
#pragma unroll
    for (int i = 0; i < 2; i++)
        bR[i] = *reinterpret_cast<const float4*>(bbase + (size_t)(lr + 32 * i) * HID + lc);

    for (int kc = 0; kc < HID / 32; kc++) {
        __syncthreads();
#pragma unroll
        for (int i = 0; i < 4; i++) {
            int r = lr + 32 * i;
            *reinterpret_cast<uint2*>(&sAh[r * SP + lc]) = aHR[i];
            *reinterpret_cast<uint2*>(&sAl[r * SP + lc]) = aLR[i];
        }
#pragma unroll
        for (int i = 0; i < 2; i++) {
            uint2 h, l; split4(bR[i], h, l);
            int r = lr + 32 * i;
            *reinterpret_cast<uint2*>(&sBh[r * SP + lc]) = h;
            *reinterpret_cast<uint2*>(&sBl[r * SP + lc]) = l;
        }
        __syncthreads();

        if (kc + 1 < HID / 32) {
            int k0 = (kc + 1) * 32;
#pragma unroll
            for (int i = 0; i < 4; i++) {
                size_t off = (size_t)(lr + 32 * i) * HID + k0 + lc;
                aHR[i] = *reinterpret_cast<const uint2*>(ahg + off);
                aLR[i] = *reinterpret_cast<const uint2*>(alg + off);
            }
#pragma unroll
            for (int i = 0; i < 2; i++)
                bR[i] = *reinterpret_cast<const float4*>(bbase + (size_t)(lr + 32 * i) * HID + k0 + lc);
        }

#pragma unroll
        for (int ks = 0; ks < 2; ks++) {
            const uint32_t kb = (uint32_t)(ks * 32);
            uint32_t ah[2][4], al[2][4];
#pragma unroll
            for (int mt = 0; mt < 2; mt++) {
                uint32_t off = aoff0 + (uint32_t)(mt * 16 * SP * 2) + kb;
                ldsm4(ah[mt][0], ah[mt][1], ah[mt][2], ah[mt][3], uAh + off);
                ldsm4(al[mt][0], al[mt][1], al[mt][2], al[mt][3], uAl + off);
            }
            uint32_t bh[2][4], bl[2][4];
#pragma unroll
            for (int np = 0; np < 2; np++) {
                uint32_t off = boff0 + (uint32_t)(np * 16 * SP * 2) + kb;
                ldsm4(bh[np][0], bh[np][1], bh[np][2], bh[np][3], uBh + off);
                ldsm4(bl[np][0], bl[np][1], bl[np][2], bl[np][3], uBl + off);
            }
#pragma unroll
            for (int mt = 0; mt < 2; mt++) {
#pragma unroll
                for (int nt = 0; nt < 4; nt++) {
                    int np = nt >> 1, s = (nt & 1) * 2;
                    mma_bf16(acc[mt][nt], ah[mt], bh[np][s], bh[np][s + 1]);
                    mma_bf16(acc[mt][nt], ah[mt], bl[np][s], bl[np][s + 1]);
                    mma_bf16(acc[mt][nt], al[mt], bh[np][s], bh[np][s + 1]);
                }
            }
        }
    }

    const int er = lane >> 2;
    const int ec = (lane & 3) * 2;
#pragma unroll
    for (int mt = 0; mt < 2; mt++) {
#pragma unroll
        for (int half = 0; half < 2; half++) {
            int m = m0 + mb + mt * 16 + er + half * 8;
            if (m >= cnt) continue;
            float* yr = g_ypair + (size_t)((e * T_TOK) + m) * DIM + n0 + nb;
#pragma unroll
            for (int nt = 0; nt < 4; nt++) {
                float2 v = make_float2(acc[mt][nt][half * 2 + 0], acc[mt][nt][half * 2 + 1]);
                *reinterpret_cast<float2*>(yr + nt * 8 + ec) = v;
            }
        }
    }
}

// ============================ combine ============================
__global__ __launch_bounds__(256) void combine_kernel(float* __restrict__ out)
{
    const int D4 = DIM / 4;
    int i = blockIdx.x * blockDim.x + threadIdx.x;
    if (i >= T_TOK * D4) return;
    int t = i / D4;
    int r = i - t * D4;
    int s0 = g_token_pairs[t * 2 + 0];
    int s1 = g_token_pairs[t * 2 + 1];
    float g0 = g_token_gate[t * 2 + 0];
    float g1 = g_token_gate[t * 2 + 1];
    const float4* y0 = reinterpret_cast<const float4*>(g_ypair) + (size_t)s0 * D4 + r;
    const float4* y1 = reinterpret_cast<const float4*>(g_ypair) + (size_t)s1 * D4 + r;
    float4 a = *y0, b = *y1, o;
    o.x = g0 * a.x + g1 * b.x;
    o.y = g0 * a.y + g1 * b.y;
    o.z = g0 * a.z + g1 * b.z;
    o.w = g0 * a.w + g1 * b.w;
    reinterpret_cast<float4*>(out)[i] = o;
}

// ============================ launch ============================
extern "C" void kernel_launch(void* const* d_in, const int* in_sizes, int n_in,
                              void* d_out, int out_size) {
    (void)in_sizes; (void)n_in; (void)out_size;
    const float* x  = (const float*)d_in[0];
    const float* rw = (const float*)d_in[1];
    const float* w1 = (const float*)d_in[2];
    const float* w3 = (const float*)d_in[3];
    const float* w2 = (const float*)d_in[4];
    float* out = (float*)d_out;

    zero_counts_kernel<<<1, 32>>>();
    router_kernel<<<T_TOK / 8, 256>>>(x, rw);
    aux_kernel<<<1, 256>>>(out);
    ffn_h_mma<<<dim3(HID / 64, T_TOK / 128, NEXP), 256>>>(x, w1, w3);
    ffn_y_mma<<<dim3(DIM / 64, T_TOK / 128, NEXP), 256>>>(w2);
    combine_kernel<<<(T_TOK * (DIM / 4) + 255) / 256, 256>>>(out);
}